// round 16
// baseline (speedup 1.0000x reference)
#include <cuda_runtime.h>
#include <cuda_fp16.h>
#include <cstdint>

#define CDIM 256
#define NSEG 65536
#define NB 8
#define GSPLIT 16                         // per-batch K splits
#define KCHUNK (NSEG / GSPLIT)            // 4096 K per CTA
#define GCH 64
#define GNCH (KCHUNK / GCH)               // 64 chunks per gram CTA
#define BUFB (2 * 32768)                  // one H/M buffer set: 64 KB (fp16 2-way split)
#define GRAM_SMEM (1024 + 2 * BUFB)       // 132,096 B (double-buffered)

#if defined(__CUDA_ARCH_FEAT_SM103_ALL) || defined(__CUDA_ARCH_FEAT_SM100_ALL)
#define HAS_TC 1
#else
#define HAS_TC 0
#endif

__device__ float g_partial[(size_t)GSPLIT * NB * CDIM * CDIM]; // 32 MB
__device__ int   g_cnt[NB * CDIM];
__device__ int   g_sp_idx[NB * CDIM * CDIM];
__device__ float g_sp_val[NB * CDIM * CDIM];

#if HAS_TC
#define MBAR_WAIT(m, par) do { \
    uint32_t _m = (uint32_t)(m), _p = (uint32_t)(par), _d; \
    asm volatile("{\n\t.reg .pred p;\n\t" \
        "mbarrier.try_wait.parity.acquire.cta.shared::cta.b64 p, [%1], %2;\n\t" \
        "selp.b32 %0, 1, 0, p;\n\t}" : "=r"(_d) : "r"(_m), "r"(_p) : "memory"); \
    if (!_d) { \
        asm volatile("{\n\t.reg .pred P1;\n\t" \
            "WL_%=:\n\t" \
            "mbarrier.try_wait.parity.acquire.cta.shared::cta.b64 P1, [%0], %1, 0x989680;\n\t" \
            "@P1 bra.uni WD_%=;\n\tbra.uni WL_%=;\n\tWD_%=:\n\t}" \
            :: "r"(_m), "r"(_p) : "memory"); \
    } } while (0)
#endif

// ---------------------------------------------------------------------------
// Warp-specialized tcgen05 gram (R13-proven, 2-stage). 288 threads: warps
// 0-7 load+convert (2-way FP16 split into SW128 smem), warp 8 issues MMAs.
// 3 split terms (hh, hm, mh). Symmetry: D0 = rows 0-127 x cols 0-255
// (N=256), D1 = rows 128-255 x cols 128-255 (N=128, A AND B descs +1024);
// block (r>=128, c<128) read transposed in softmax.
// ---------------------------------------------------------------------------
__global__ void __launch_bounds__(288, 1) gram_tc(const float* __restrict__ feats) {
#if HAS_TC
    extern __shared__ __align__(1024) char smem[];
    uint32_t sb;
    asm("{ .reg .u64 t; cvta.to.shared.u64 t, %1; cvt.u32.u64 %0, t; }" : "=r"(sb) : "l"(smem));
    const int tid = threadIdx.x, wid = tid >> 5;
    const float* X = feats + (size_t)blockIdx.y * CDIM * NSEG;
    const int k0 = blockIdx.x * KCHUNK;

    // mbarriers: empty0 @+8, empty1 @+16, full0 @+24, full1 @+32
    if (wid == 8) {
        asm volatile("tcgen05.alloc.cta_group::1.sync.aligned.shared::cta.b32 [%0], %1;"
                     :: "r"(sb), "r"(512u) : "memory");
        if ((tid & 31) == 0) {
            asm volatile("mbarrier.init.shared.b64 [%0], %1;" :: "r"(sb + 8),  "r"(1u)   : "memory");
            asm volatile("mbarrier.init.shared.b64 [%0], %1;" :: "r"(sb + 16), "r"(1u)   : "memory");
            asm volatile("mbarrier.init.shared.b64 [%0], %1;" :: "r"(sb + 24), "r"(256u) : "memory");
            asm volatile("mbarrier.init.shared.b64 [%0], %1;" :: "r"(sb + 32), "r"(256u) : "memory");
        }
    }
    __syncthreads();
    uint32_t tmem;
    asm volatile("ld.shared.b32 %0, [%1];" : "=r"(tmem) : "r"(sb));

    const uint64_t DBASE = 0x4000404000010000ull;  // SW128 K-major, v1, SBO=64, LBO=1
    // dtype F32, atype/btype FP16 (=0), N, M=128
    const uint32_t IDESC0 = (1u << 4) | (32u << 17) | (8u << 24); // N=256
    const uint32_t IDESC1 = (1u << 4) | (16u << 17) | (8u << 24); // N=128

    if (wid < 8) {
        float4 rg[16];
#pragma unroll
        for (int p = 0; p < 16; p++) {
            int g = p * 256 + tid;
            rg[p] = *(const float4*)(X + (size_t)(g >> 4) * NSEG + k0 + (g & 15) * 4);
        }
        for (int i = 0; i < GNCH; i++) {
            const int s = i & 1;
            if (i >= 2) MBAR_WAIT(sb + 8 + s * 8, ((i - 2) >> 1) & 1);   // empty[s]
            const uint32_t H = sb + 1024 + s * BUFB, M = H + 32768;
#pragma unroll
            for (int p = 0; p < 16; p++) {
                int g = p * 256 + tid;
                float4 v = rg[p];
                __half2 h0 = __floats2half2_rn(v.x, v.y);
                __half2 h1 = __floats2half2_rn(v.z, v.w);
                float2 hf0 = __half22float2(h0), hf1 = __half22float2(h1);
                __half2 m0 = __floats2half2_rn(v.x - hf0.x, v.y - hf0.y);
                __half2 m1 = __floats2half2_rn(v.z - hf1.x, v.w - hf1.y);
                uint32_t off = (uint32_t)((g >> 4) * 128 + (g & 15) * 8);
                off ^= (off >> 3) & 0x70;
                asm volatile("st.shared.v2.b32 [%0], {%1,%2};" :: "r"(H + off),
                             "r"(*(uint32_t*)&h0), "r"(*(uint32_t*)&h1) : "memory");
                asm volatile("st.shared.v2.b32 [%0], {%1,%2};" :: "r"(M + off),
                             "r"(*(uint32_t*)&m0), "r"(*(uint32_t*)&m1) : "memory");
            }
            asm volatile("fence.proxy.async.shared::cta;" ::: "memory");
            asm volatile("mbarrier.arrive.shared.b64 _, [%0];" :: "r"(sb + 24 + s * 8) : "memory");
            if (i + 1 < GNCH) {
                const int kc = k0 + (i + 1) * GCH;
#pragma unroll
                for (int p = 0; p < 16; p++) {
                    int g = p * 256 + tid;
                    rg[p] = *(const float4*)(X + (size_t)(g >> 4) * NSEG + kc + (g & 15) * 4);
                }
            }
        }
    } else {
        uint32_t is_e;
        asm volatile("{\n\t.reg .pred p;\n\telect.sync _|p, 0xFFFFFFFF;\n\t"
                     "selp.b32 %0, 1, 0, p;\n\t}" : "=r"(is_e));
        for (int i = 0; i < GNCH; i++) {
            const int s = i & 1;
            MBAR_WAIT(sb + 24 + s * 8, (i >> 1) & 1);                    // full[s]
            if (is_e) {
                const uint32_t H = sb + 1024 + s * BUFB, M = H + 32768;
                uint64_t dh = DBASE | ((H >> 4) & 0x3FFF);
                uint64_t dm = DBASE | ((M >> 4) & 0x3FFF);
#pragma unroll
                for (int ks = 0; ks < 4; ks++) {
                    uint64_t oh = dh + 2 * ks, om = dm + 2 * ks;
                    bool f = (i == 0 && ks == 0);
#pragma unroll
                    for (int hf = 0; hf < 2; hf++) {
                        uint32_t d = tmem + hf * 256;
                        uint32_t idc = hf ? IDESC1 : IDESC0;
                        uint64_t ah = oh + hf * 1024, am = om + hf * 1024;
                        // 3 terms: hh, hm, mh; B carries the same hf offset as A
                        uint64_t av[3] = {ah, ah, am};
                        uint64_t bv[3] = {ah, am, ah};
#pragma unroll
                        for (int t = 0; t < 3; t++) {
                            uint32_t en = (f && t == 0) ? 0u : 1u;
                            asm volatile("{\n\t.reg .pred p;\n\tsetp.ne.u32 p, %4, 0;\n\t"
                                "tcgen05.mma.cta_group::1.kind::f16 [%0], %1, %2, %3, {%5,%5,%5,%5}, p;\n\t}"
                                :: "r"(d), "l"(av[t]), "l"(bv[t]), "r"(idc), "r"(en), "r"(0u)
                                : "memory");
                        }
                    }
                }
                asm volatile("tcgen05.commit.cta_group::1.mbarrier::arrive::one.shared::cluster.b64 [%0];"
                             :: "r"(sb + 8 + s * 8) : "memory");
            }
        }
    }

    MBAR_WAIT(sb + 8,  ((GNCH - 2) >> 1) & 1);
    MBAR_WAIT(sb + 16, ((GNCH - 1) >> 1) & 1);
    asm volatile("tcgen05.fence::after_thread_sync;" ::: "memory");

    float* P = g_partial + ((size_t)blockIdx.x * NB + blockIdx.y) * (CDIM * CDIM);
    if (wid < 4) {
        const int row = wid * 32 + (tid & 31);
#pragma unroll 1
        for (int cg = 0; cg < 8; cg++) {
            uint32_t r[32];
            asm volatile("tcgen05.ld.sync.aligned.32x32b.x32.b32 "
                "{%0,%1,%2,%3,%4,%5,%6,%7,%8,%9,%10,%11,%12,%13,%14,%15,"
                "%16,%17,%18,%19,%20,%21,%22,%23,%24,%25,%26,%27,%28,%29,%30,%31}, [%32];"
                : "=r"(r[0]),"=r"(r[1]),"=r"(r[2]),"=r"(r[3]),"=r"(r[4]),"=r"(r[5]),
                  "=r"(r[6]),"=r"(r[7]),"=r"(r[8]),"=r"(r[9]),"=r"(r[10]),"=r"(r[11]),
                  "=r"(r[12]),"=r"(r[13]),"=r"(r[14]),"=r"(r[15]),"=r"(r[16]),"=r"(r[17]),
                  "=r"(r[18]),"=r"(r[19]),"=r"(r[20]),"=r"(r[21]),"=r"(r[22]),"=r"(r[23]),
                  "=r"(r[24]),"=r"(r[25]),"=r"(r[26]),"=r"(r[27]),"=r"(r[28]),"=r"(r[29]),
                  "=r"(r[30]),"=r"(r[31]) : "r"(tmem + cg * 32));
            asm volatile("tcgen05.wait::ld.sync.aligned;" ::: "memory");
            uint4* dst = (uint4*)(P + (size_t)row * CDIM + cg * 32);
#pragma unroll
            for (int q = 0; q < 8; q++)
                dst[q] = make_uint4(r[q * 4], r[q * 4 + 1], r[q * 4 + 2], r[q * 4 + 3]);
        }
    } else if (wid < 8) {
        const int row = 128 + (wid & 3) * 32 + (tid & 31);
#pragma unroll 1
        for (int cg = 0; cg < 4; cg++) {
            uint32_t r[32];
            asm volatile("tcgen05.ld.sync.aligned.32x32b.x32.b32 "
                "{%0,%1,%2,%3,%4,%5,%6,%7,%8,%9,%10,%11,%12,%13,%14,%15,"
                "%16,%17,%18,%19,%20,%21,%22,%23,%24,%25,%26,%27,%28,%29,%30,%31}, [%32];"
                : "=r"(r[0]),"=r"(r[1]),"=r"(r[2]),"=r"(r[3]),"=r"(r[4]),"=r"(r[5]),
                  "=r"(r[6]),"=r"(r[7]),"=r"(r[8]),"=r"(r[9]),"=r"(r[10]),"=r"(r[11]),
                  "=r"(r[12]),"=r"(r[13]),"=r"(r[14]),"=r"(r[15]),"=r"(r[16]),"=r"(r[17]),
                  "=r"(r[18]),"=r"(r[19]),"=r"(r[20]),"=r"(r[21]),"=r"(r[22]),"=r"(r[23]),
                  "=r"(r[24]),"=r"(r[25]),"=r"(r[26]),"=r"(r[27]),"=r"(r[28]),"=r"(r[29]),
                  "=r"(r[30]),"=r"(r[31]) : "r"(tmem + 256 + cg * 32));
            asm volatile("tcgen05.wait::ld.sync.aligned;" ::: "memory");
            uint4* dst = (uint4*)(P + (size_t)row * CDIM + 128 + cg * 32);
#pragma unroll
            for (int q = 0; q < 8; q++)
                dst[q] = make_uint4(r[q * 4], r[q * 4 + 1], r[q * 4 + 2], r[q * 4 + 3]);
        }
    }
    __syncthreads();
    if (wid == 8)
        asm volatile("tcgen05.dealloc.cta_group::1.sync.aligned.b32 %0, %1;"
                     :: "r"(tmem), "r"(512u));
#endif
}

// ---------------------------------------------------------------------------
// Softmax + exact-sparsity extraction. Symmetric partials: block
// (r>=128, d<128) read as its transpose.
// ---------------------------------------------------------------------------
__global__ void softmax_kernel(const float* __restrict__ gamma) {
    const int b = blockIdx.x >> 8, r = blockIdx.x & 255;
    const int d = threadIdx.x;
    const bool direct = (r < 128) || (d >= 128);
    const int rr = direct ? r : d;
    const int dd = direct ? d : r;
    const size_t base = (size_t)b * (CDIM * CDIM) + (size_t)rr * CDIM + dd;

    float e = 0.f;
#pragma unroll
    for (int s = 0; s < GSPLIT; s++)
        e += g_partial[(size_t)s * (NB * CDIM * CDIM) + base];

    __shared__ float red[CDIM];
    __shared__ int wb[9];
    red[d] = e;
    __syncthreads();
    for (int s = 128; s > 0; s >>= 1) {
        if (d < s) red[d] = fminf(red[d], red[d + s]);
        __syncthreads();
    }
    float minv = red[0];
    __syncthreads();
    float v = expf(minv - e);
    red[d] = v;
    __syncthreads();
    for (int s = 128; s > 0; s >>= 1) {
        if (d < s) red[d] += red[d + s];
        __syncthreads();
    }
    float S = red[0];

    bool keep = (e - minv) < 100.0f;
    unsigned msk = __ballot_sync(0xffffffffu, keep);
    int lane = d & 31, w = d >> 5;
    if (lane == 0) wb[w] = __popc(msk);
    __syncthreads();
    if (d == 0) {
        int acc = 0;
        for (int t = 0; t < 8; t++) { int x = wb[t]; wb[t] = acc; acc += x; }
        wb[8] = acc;
    }
    __syncthreads();
    const int row = blockIdx.x;
    if (keep) {
        int pos = wb[w] + __popc(msk & ((1u << lane) - 1));
        g_sp_idx[row * CDIM + pos] = d;
        g_sp_val[row * CDIM + pos] = gamma[0] * v / S;
    }
    if (d == 0) g_cnt[row] = wb[8];
}

// ---------------------------------------------------------------------------
// Sparse out: y[c,j] = sum_k val[c,k]*x[d_k,j] + x[c,j]
// 8 float4 per thread (j-window 8192) for doubled gather MLP; PLAIN cached
// loads everywhere (the R10 regression was __ldcs, tested in isolation here);
// __stcs only on the write-once Y store.
// ---------------------------------------------------------------------------
__global__ void __launch_bounds__(256) out_sparse(const float* __restrict__ feats,
                                                  float* __restrict__ out) {
    const int c = blockIdx.x, b = blockIdx.z;
    const int row = b * CDIM + c;
    const float* Xb = feats + (size_t)b * CDIM * NSEG;
    const int j0 = blockIdx.y * 8192 + threadIdx.x * 4;

    float4 acc[8];
#pragma unroll
    for (int q = 0; q < 8; q++)
        acc[q] = *(const float4*)(Xb + (size_t)c * NSEG + j0 + q * 1024);

    const int cnt = g_cnt[row];
    for (int k = 0; k < cnt; k++) {
        const int dd = g_sp_idx[row * CDIM + k];
        const float v = g_sp_val[row * CDIM + k];
        const float* xp = Xb + (size_t)dd * NSEG + j0;
#pragma unroll
        for (int q = 0; q < 8; q++) {
            float4 x4 = *(const float4*)(xp + q * 1024);
            acc[q].x = fmaf(v, x4.x, acc[q].x);
            acc[q].y = fmaf(v, x4.y, acc[q].y);
            acc[q].z = fmaf(v, x4.z, acc[q].z);
            acc[q].w = fmaf(v, x4.w, acc[q].w);
        }
    }
    float* yp = out + (size_t)b * CDIM * NSEG + (size_t)c * NSEG + j0;
#pragma unroll
    for (int q = 0; q < 8; q++)
        __stcs((float4*)(yp + q * 1024), acc[q]);
}

// ---------------------------------------------------------------------------
extern "C" void kernel_launch(void* const* d_in, const int* in_sizes, int n_in,
                              void* d_out, int out_size) {
    const float* feats = (const float*)d_in[0];
    const float* gamma = (const float*)d_in[1];
    float* out = (float*)d_out;

    cudaFuncSetAttribute(gram_tc, cudaFuncAttributeMaxDynamicSharedMemorySize, GRAM_SMEM);
    gram_tc<<<dim3(GSPLIT, NB), 288, GRAM_SMEM>>>(feats);
    softmax_kernel<<<NB * CDIM, CDIM>>>(gamma);
    out_sparse<<<dim3(CDIM, 8, NB), 256>>>(feats, out);
}

// round 17
// speedup vs baseline: 1.0748x; 1.0748x over previous
#include <cuda_runtime.h>
#include <cuda_fp16.h>
#include <cstdint>

#define CDIM 256
#define NSEG 65536
#define NB 8
#define GSPLIT 16                         // per-batch K splits
#define KCHUNK (NSEG / GSPLIT)            // 4096 K per CTA
#define GCH 64
#define GNCH (KCHUNK / GCH)               // 64 chunks per gram CTA
#define BUFB (2 * 32768)                  // one H/M buffer set: 64 KB (fp16 2-way split)
#define GRAM_SMEM (1024 + 2 * BUFB)       // 132,096 B (double-buffered)

#if defined(__CUDA_ARCH_FEAT_SM103_ALL) || defined(__CUDA_ARCH_FEAT_SM100_ALL)
#define HAS_TC 1
#else
#define HAS_TC 0
#endif

__device__ float g_partial[(size_t)GSPLIT * NB * CDIM * CDIM]; // 32 MB
__device__ int   g_cnt[NB * CDIM];
__device__ int   g_sp_idx[NB * CDIM * CDIM];
__device__ float g_sp_val[NB * CDIM * CDIM];

#if HAS_TC
#define MBAR_WAIT(m, par) do { \
    uint32_t _m = (uint32_t)(m), _p = (uint32_t)(par), _d; \
    asm volatile("{\n\t.reg .pred p;\n\t" \
        "mbarrier.try_wait.parity.acquire.cta.shared::cta.b64 p, [%1], %2;\n\t" \
        "selp.b32 %0, 1, 0, p;\n\t}" : "=r"(_d) : "r"(_m), "r"(_p) : "memory"); \
    if (!_d) { \
        asm volatile("{\n\t.reg .pred P1;\n\t" \
            "WL_%=:\n\t" \
            "mbarrier.try_wait.parity.acquire.cta.shared::cta.b64 P1, [%0], %1, 0x989680;\n\t" \
            "@P1 bra.uni WD_%=;\n\tbra.uni WL_%=;\n\tWD_%=:\n\t}" \
            :: "r"(_m), "r"(_p) : "memory"); \
    } } while (0)
#endif

// ---------------------------------------------------------------------------
// Warp-specialized tcgen05 gram (R13-proven, 2-stage). 288 threads: warps
// 0-7 load+convert (2-way FP16 split into SW128 smem), warp 8 issues MMAs.
// 3 split terms (hh, hm, mh). Symmetry: D0 = rows 0-127 x cols 0-255
// (N=256), D1 = rows 128-255 x cols 128-255 (N=128, A AND B descs +1024).
// Epilogue writes the FULL symmetric partial: warps 0-3 additionally store
// the transpose of D0's cols 128-255 into the (r>=128, c<128) quadrant
// (coalesced: fixed reg -> 32 lanes hit 128 contiguous bytes), so softmax
// reads everything directly.
// ---------------------------------------------------------------------------
__global__ void __launch_bounds__(288, 1) gram_tc(const float* __restrict__ feats) {
#if HAS_TC
    extern __shared__ __align__(1024) char smem[];
    uint32_t sb;
    asm("{ .reg .u64 t; cvta.to.shared.u64 t, %1; cvt.u32.u64 %0, t; }" : "=r"(sb) : "l"(smem));
    const int tid = threadIdx.x, wid = tid >> 5;
    const float* X = feats + (size_t)blockIdx.y * CDIM * NSEG;
    const int k0 = blockIdx.x * KCHUNK;

    // mbarriers: empty0 @+8, empty1 @+16, full0 @+24, full1 @+32
    if (wid == 8) {
        asm volatile("tcgen05.alloc.cta_group::1.sync.aligned.shared::cta.b32 [%0], %1;"
                     :: "r"(sb), "r"(512u) : "memory");
        if ((tid & 31) == 0) {
            asm volatile("mbarrier.init.shared.b64 [%0], %1;" :: "r"(sb + 8),  "r"(1u)   : "memory");
            asm volatile("mbarrier.init.shared.b64 [%0], %1;" :: "r"(sb + 16), "r"(1u)   : "memory");
            asm volatile("mbarrier.init.shared.b64 [%0], %1;" :: "r"(sb + 24), "r"(256u) : "memory");
            asm volatile("mbarrier.init.shared.b64 [%0], %1;" :: "r"(sb + 32), "r"(256u) : "memory");
        }
    }
    __syncthreads();
    uint32_t tmem;
    asm volatile("ld.shared.b32 %0, [%1];" : "=r"(tmem) : "r"(sb));

    const uint64_t DBASE = 0x4000404000010000ull;  // SW128 K-major, v1, SBO=64, LBO=1
    // dtype F32, atype/btype FP16 (=0), N, M=128
    const uint32_t IDESC0 = (1u << 4) | (32u << 17) | (8u << 24); // N=256
    const uint32_t IDESC1 = (1u << 4) | (16u << 17) | (8u << 24); // N=128

    if (wid < 8) {
        float4 rg[16];
#pragma unroll
        for (int p = 0; p < 16; p++) {
            int g = p * 256 + tid;
            rg[p] = *(const float4*)(X + (size_t)(g >> 4) * NSEG + k0 + (g & 15) * 4);
        }
        for (int i = 0; i < GNCH; i++) {
            const int s = i & 1;
            if (i >= 2) MBAR_WAIT(sb + 8 + s * 8, ((i - 2) >> 1) & 1);   // empty[s]
            const uint32_t H = sb + 1024 + s * BUFB, M = H + 32768;
#pragma unroll
            for (int p = 0; p < 16; p++) {
                int g = p * 256 + tid;
                float4 v = rg[p];
                __half2 h0 = __floats2half2_rn(v.x, v.y);
                __half2 h1 = __floats2half2_rn(v.z, v.w);
                float2 hf0 = __half22float2(h0), hf1 = __half22float2(h1);
                __half2 m0 = __floats2half2_rn(v.x - hf0.x, v.y - hf0.y);
                __half2 m1 = __floats2half2_rn(v.z - hf1.x, v.w - hf1.y);
                uint32_t off = (uint32_t)((g >> 4) * 128 + (g & 15) * 8);
                off ^= (off >> 3) & 0x70;
                asm volatile("st.shared.v2.b32 [%0], {%1,%2};" :: "r"(H + off),
                             "r"(*(uint32_t*)&h0), "r"(*(uint32_t*)&h1) : "memory");
                asm volatile("st.shared.v2.b32 [%0], {%1,%2};" :: "r"(M + off),
                             "r"(*(uint32_t*)&m0), "r"(*(uint32_t*)&m1) : "memory");
            }
            asm volatile("fence.proxy.async.shared::cta;" ::: "memory");
            asm volatile("mbarrier.arrive.shared.b64 _, [%0];" :: "r"(sb + 24 + s * 8) : "memory");
            if (i + 1 < GNCH) {
                const int kc = k0 + (i + 1) * GCH;
#pragma unroll
                for (int p = 0; p < 16; p++) {
                    int g = p * 256 + tid;
                    rg[p] = *(const float4*)(X + (size_t)(g >> 4) * NSEG + kc + (g & 15) * 4);
                }
            }
        }
    } else {
        uint32_t is_e;
        asm volatile("{\n\t.reg .pred p;\n\telect.sync _|p, 0xFFFFFFFF;\n\t"
                     "selp.b32 %0, 1, 0, p;\n\t}" : "=r"(is_e));
        for (int i = 0; i < GNCH; i++) {
            const int s = i & 1;
            MBAR_WAIT(sb + 24 + s * 8, (i >> 1) & 1);                    // full[s]
            if (is_e) {
                const uint32_t H = sb + 1024 + s * BUFB, M = H + 32768;
                uint64_t dh = DBASE | ((H >> 4) & 0x3FFF);
                uint64_t dm = DBASE | ((M >> 4) & 0x3FFF);
#pragma unroll
                for (int ks = 0; ks < 4; ks++) {
                    uint64_t oh = dh + 2 * ks, om = dm + 2 * ks;
                    bool f = (i == 0 && ks == 0);
#pragma unroll
                    for (int hf = 0; hf < 2; hf++) {
                        uint32_t d = tmem + hf * 256;
                        uint32_t idc = hf ? IDESC1 : IDESC0;
                        uint64_t ah = oh + hf * 1024, am = om + hf * 1024;
                        // 3 terms: hh, hm, mh; B carries the same hf offset as A
                        uint64_t av[3] = {ah, ah, am};
                        uint64_t bv[3] = {ah, am, ah};
#pragma unroll
                        for (int t = 0; t < 3; t++) {
                            uint32_t en = (f && t == 0) ? 0u : 1u;
                            asm volatile("{\n\t.reg .pred p;\n\tsetp.ne.u32 p, %4, 0;\n\t"
                                "tcgen05.mma.cta_group::1.kind::f16 [%0], %1, %2, %3, {%5,%5,%5,%5}, p;\n\t}"
                                :: "r"(d), "l"(av[t]), "l"(bv[t]), "r"(idc), "r"(en), "r"(0u)
                                : "memory");
                        }
                    }
                }
                asm volatile("tcgen05.commit.cta_group::1.mbarrier::arrive::one.shared::cluster.b64 [%0];"
                             :: "r"(sb + 8 + s * 8) : "memory");
            }
        }
    }

    MBAR_WAIT(sb + 8,  ((GNCH - 2) >> 1) & 1);
    MBAR_WAIT(sb + 16, ((GNCH - 1) >> 1) & 1);
    asm volatile("tcgen05.fence::after_thread_sync;" ::: "memory");

    float* P = g_partial + ((size_t)blockIdx.x * NB + blockIdx.y) * (CDIM * CDIM);
    if (wid < 4) {
        const int row = wid * 32 + (tid & 31);
#pragma unroll 1
        for (int cg = 0; cg < 8; cg++) {
            uint32_t r[32];
            asm volatile("tcgen05.ld.sync.aligned.32x32b.x32.b32 "
                "{%0,%1,%2,%3,%4,%5,%6,%7,%8,%9,%10,%11,%12,%13,%14,%15,"
                "%16,%17,%18,%19,%20,%21,%22,%23,%24,%25,%26,%27,%28,%29,%30,%31}, [%32];"
                : "=r"(r[0]),"=r"(r[1]),"=r"(r[2]),"=r"(r[3]),"=r"(r[4]),"=r"(r[5]),
                  "=r"(r[6]),"=r"(r[7]),"=r"(r[8]),"=r"(r[9]),"=r"(r[10]),"=r"(r[11]),
                  "=r"(r[12]),"=r"(r[13]),"=r"(r[14]),"=r"(r[15]),"=r"(r[16]),"=r"(r[17]),
                  "=r"(r[18]),"=r"(r[19]),"=r"(r[20]),"=r"(r[21]),"=r"(r[22]),"=r"(r[23]),
                  "=r"(r[24]),"=r"(r[25]),"=r"(r[26]),"=r"(r[27]),"=r"(r[28]),"=r"(r[29]),
                  "=r"(r[30]),"=r"(r[31]) : "r"(tmem + cg * 32));
            asm volatile("tcgen05.wait::ld.sync.aligned;" ::: "memory");
            uint4* dst = (uint4*)(P + (size_t)row * CDIM + cg * 32);
#pragma unroll
            for (int q = 0; q < 8; q++)
                dst[q] = make_uint4(r[q * 4], r[q * 4 + 1], r[q * 4 + 2], r[q * 4 + 3]);
            if (cg >= 4) {
                // transpose-write D0 cols 128-255 into quadrant (r>=128, c<128):
                // for fixed q, 32 lanes write P[col][row..row+31] -> coalesced 128B
#pragma unroll
                for (int q = 0; q < 32; q++) {
                    int col = cg * 32 + q;              // 128..255
                    P[(size_t)col * CDIM + row] = __uint_as_float(r[q]);
                }
            }
        }
    } else if (wid < 8) {
        const int row = 128 + (wid & 3) * 32 + (tid & 31);
#pragma unroll 1
        for (int cg = 0; cg < 4; cg++) {
            uint32_t r[32];
            asm volatile("tcgen05.ld.sync.aligned.32x32b.x32.b32 "
                "{%0,%1,%2,%3,%4,%5,%6,%7,%8,%9,%10,%11,%12,%13,%14,%15,"
                "%16,%17,%18,%19,%20,%21,%22,%23,%24,%25,%26,%27,%28,%29,%30,%31}, [%32];"
                : "=r"(r[0]),"=r"(r[1]),"=r"(r[2]),"=r"(r[3]),"=r"(r[4]),"=r"(r[5]),
                  "=r"(r[6]),"=r"(r[7]),"=r"(r[8]),"=r"(r[9]),"=r"(r[10]),"=r"(r[11]),
                  "=r"(r[12]),"=r"(r[13]),"=r"(r[14]),"=r"(r[15]),"=r"(r[16]),"=r"(r[17]),
                  "=r"(r[18]),"=r"(r[19]),"=r"(r[20]),"=r"(r[21]),"=r"(r[22]),"=r"(r[23]),
                  "=r"(r[24]),"=r"(r[25]),"=r"(r[26]),"=r"(r[27]),"=r"(r[28]),"=r"(r[29]),
                  "=r"(r[30]),"=r"(r[31]) : "r"(tmem + 256 + cg * 32));
            asm volatile("tcgen05.wait::ld.sync.aligned;" ::: "memory");
            uint4* dst = (uint4*)(P + (size_t)row * CDIM + 128 + cg * 32);
#pragma unroll
            for (int q = 0; q < 8; q++)
                dst[q] = make_uint4(r[q * 4], r[q * 4 + 1], r[q * 4 + 2], r[q * 4 + 3]);
        }
    }
    __syncthreads();
    if (wid == 8)
        asm volatile("tcgen05.dealloc.cta_group::1.sync.aligned.b32 %0, %1;"
                     :: "r"(tmem), "r"(512u));
#endif
}

// ---------------------------------------------------------------------------
// Softmax + exact-sparsity extraction. Partials now FULL matrices — all
// reads direct and coalesced.
// ---------------------------------------------------------------------------
__global__ void softmax_kernel(const float* __restrict__ gamma) {
    const int b = blockIdx.x >> 8, r = blockIdx.x & 255;
    const int d = threadIdx.x;
    const size_t base = (size_t)b * (CDIM * CDIM) + (size_t)r * CDIM + d;

    float e = 0.f;
#pragma unroll
    for (int s = 0; s < GSPLIT; s++)
        e += g_partial[(size_t)s * (NB * CDIM * CDIM) + base];

    __shared__ float red[CDIM];
    __shared__ int wb[9];
    red[d] = e;
    __syncthreads();
    for (int s = 128; s > 0; s >>= 1) {
        if (d < s) red[d] = fminf(red[d], red[d + s]);
        __syncthreads();
    }
    float minv = red[0];
    __syncthreads();
    float v = expf(minv - e);
    red[d] = v;
    __syncthreads();
    for (int s = 128; s > 0; s >>= 1) {
        if (d < s) red[d] += red[d + s];
        __syncthreads();
    }
    float S = red[0];

    bool keep = (e - minv) < 100.0f;
    unsigned msk = __ballot_sync(0xffffffffu, keep);
    int lane = d & 31, w = d >> 5;
    if (lane == 0) wb[w] = __popc(msk);
    __syncthreads();
    if (d == 0) {
        int acc = 0;
        for (int t = 0; t < 8; t++) { int x = wb[t]; wb[t] = acc; acc += x; }
        wb[8] = acc;
    }
    __syncthreads();
    const int row = blockIdx.x;
    if (keep) {
        int pos = wb[w] + __popc(msk & ((1u << lane) - 1));
        g_sp_idx[row * CDIM + pos] = d;
        g_sp_val[row * CDIM + pos] = gamma[0] * v / S;
    }
    if (d == 0) g_cnt[row] = wb[8];
}

// ---------------------------------------------------------------------------
// Sparse out (R7-proven form, PINNED): y[c,j] = sum_k val[c,k]*x[d_k,j] + x[c,j]
// 4 float4 per thread, plain cached loads, __stcs only on the Y store.
// ---------------------------------------------------------------------------
__global__ void __launch_bounds__(256) out_sparse(const float* __restrict__ feats,
                                                  float* __restrict__ out) {
    const int c = blockIdx.x, b = blockIdx.z;
    const int row = b * CDIM + c;
    const float* Xb = feats + (size_t)b * CDIM * NSEG;
    const int j0 = blockIdx.y * 4096 + threadIdx.x * 4;

    float4 acc[4];
#pragma unroll
    for (int q = 0; q < 4; q++)
        acc[q] = *(const float4*)(Xb + (size_t)c * NSEG + j0 + q * 1024);

    const int cnt = g_cnt[row];
    for (int k = 0; k < cnt; k++) {
        const int dd = g_sp_idx[row * CDIM + k];
        const float v = g_sp_val[row * CDIM + k];
        const float* xp = Xb + (size_t)dd * NSEG + j0;
#pragma unroll
        for (int q = 0; q < 4; q++) {
            float4 x4 = *(const float4*)(xp + q * 1024);
            acc[q].x = fmaf(v, x4.x, acc[q].x);
            acc[q].y = fmaf(v, x4.y, acc[q].y);
            acc[q].z = fmaf(v, x4.z, acc[q].z);
            acc[q].w = fmaf(v, x4.w, acc[q].w);
        }
    }
    float* yp = out + (size_t)b * CDIM * NSEG + (size_t)c * NSEG + j0;
#pragma unroll
    for (int q = 0; q < 4; q++)
        __stcs((float4*)(yp + q * 1024), acc[q]);
}

// ---------------------------------------------------------------------------
extern "C" void kernel_launch(void* const* d_in, const int* in_sizes, int n_in,
                              void* d_out, int out_size) {
    const float* feats = (const float*)d_in[0];
    const float* gamma = (const float*)d_in[1];
    float* out = (float*)d_out;

    cudaFuncSetAttribute(gram_tc, cudaFuncAttributeMaxDynamicSharedMemorySize, GRAM_SMEM);
    gram_tc<<<dim3(GSPLIT, NB), 288, GRAM_SMEM>>>(feats);
    softmax_kernel<<<NB * CDIM, CDIM>>>(gamma);
    out_sparse<<<dim3(CDIM, 16, NB), 256>>>(feats, out);
}